// round 1
// baseline (speedup 1.0000x reference)
#include <cuda_runtime.h>
#include <math.h>

#define DIM   1024
#define HMID  512
#define HLOW  256
#define ROWS  32768   // 4 * 8192

// Scratch (device globals — allocation-free per harness rules)
__device__ float g_buf1[ROWS * HMID];   // 64 MB
__device__ float g_buf2[ROWS * HMID];   // 64 MB
__device__ float g_mu[ROWS];
__device__ float g_rstd[ROWS];

__device__ __forceinline__ float gelu_f(float v) {
    // exact erf GELU (torch default)
    return 0.5f * v * (1.0f + erff(v * 0.70710678118654752440f));
}

// ---------------------------------------------------------------------------
// Kernel 0: per-row mean / rstd for LayerNorm (folded into GEMM1 A-loads)
// ---------------------------------------------------------------------------
__global__ void rowstats_kernel(const float* __restrict__ x) {
    const int row = blockIdx.x;
    const float4* xr = reinterpret_cast<const float4*>(x + (size_t)row * DIM);
    float4 v = xr[threadIdx.x];                    // 256 threads * 4 = 1024
    float s  = v.x + v.y + v.z + v.w;
    float sq = v.x * v.x + v.y * v.y + v.z * v.z + v.w * v.w;

    __shared__ float ss[8], ssq[8];
    #pragma unroll
    for (int o = 16; o > 0; o >>= 1) {
        s  += __shfl_down_sync(0xffffffffu, s,  o);
        sq += __shfl_down_sync(0xffffffffu, sq, o);
    }
    const int warp = threadIdx.x >> 5, lane = threadIdx.x & 31;
    if (lane == 0) { ss[warp] = s; ssq[warp] = sq; }
    __syncthreads();
    if (warp == 0) {
        s  = (lane < 8) ? ss[lane]  : 0.0f;
        sq = (lane < 8) ? ssq[lane] : 0.0f;
        #pragma unroll
        for (int o = 4; o > 0; o >>= 1) {
            s  += __shfl_down_sync(0xffffffffu, s,  o);
            sq += __shfl_down_sync(0xffffffffu, sq, o);
        }
        if (lane == 0) {
            float mu  = s * (1.0f / DIM);
            float var = sq * (1.0f / DIM) - mu * mu;
            g_mu[row]   = mu;
            g_rstd[row] = rsqrtf(var + 1e-5f);
        }
    }
}

// ---------------------------------------------------------------------------
// Tiled SGEMM: C[M,N] = epilogue(A[M,K] @ B[K,N] + bias)
//   BM=BN=128, BK=8, 256 threads, 8x8 micro-tile, double-buffered smem.
//   LNA  : apply (a - mu)*rstd*gamma + beta on A loads (GEMM1)
//   EPI 0: GELU        EPI 1: + residual (final GEMM)
// M is always ROWS; K,N compile-time.
// ---------------------------------------------------------------------------
template <int K, int N, int EPI, bool LNA>
__global__ void __launch_bounds__(256, 2)
gemm_kernel(const float* __restrict__ A, const float* __restrict__ Bw,
            const float* __restrict__ bias, float* __restrict__ C,
            const float* __restrict__ gamma, const float* __restrict__ beta,
            const float* __restrict__ resid) {
    constexpr int BM = 128, BN = 128, BK = 8, TM = 8, TN = 8;
    __shared__ float As[2][BK][BM];
    __shared__ float Bs[2][BK][BN];

    const int tid = threadIdx.x;
    const int tx = tid & 15;          // 0..15 -> N
    const int ty = tid >> 4;          // 0..15 -> M
    const int bm = blockIdx.y * BM;
    const int bn = blockIdx.x * BN;

    // A-tile load mapping: 128x8 floats = 256 float4 (4 along K)
    const int arow = tid >> 1;
    const int acol = (tid & 1) * 4;
    // B-tile load mapping: 8x128 floats = 256 float4 (4 along N)
    const int brow = tid >> 5;
    const int bcol = (tid & 31) * 4;

    float mu = 0.0f, rs = 1.0f;
    if (LNA) { mu = g_mu[bm + arow]; rs = g_rstd[bm + arow]; }

    const float* Aptr = A  + (size_t)(bm + arow) * K + acol;
    const float* Bptr = Bw + (size_t)brow * N + bn + bcol;

    float acc[TM][TN];
    #pragma unroll
    for (int i = 0; i < TM; i++)
        #pragma unroll
        for (int j = 0; j < TN; j++) acc[i][j] = 0.0f;

    // ---- load tile 0 ----
    {
        float4 a = *reinterpret_cast<const float4*>(Aptr);
        if (LNA) {
            float4 g = *reinterpret_cast<const float4*>(gamma + acol);
            float4 be = *reinterpret_cast<const float4*>(beta + acol);
            a.x = (a.x - mu) * rs * g.x + be.x;
            a.y = (a.y - mu) * rs * g.y + be.y;
            a.z = (a.z - mu) * rs * g.z + be.z;
            a.w = (a.w - mu) * rs * g.w + be.w;
        }
        float4 b = *reinterpret_cast<const float4*>(Bptr);
        As[0][acol + 0][arow] = a.x;
        As[0][acol + 1][arow] = a.y;
        As[0][acol + 2][arow] = a.z;
        As[0][acol + 3][arow] = a.w;
        *reinterpret_cast<float4*>(&Bs[0][brow][bcol]) = b;
    }
    __syncthreads();

    constexpr int NT = K / BK;
    int buf = 0;
    for (int t = 0; t < NT; t++) {
        float4 a, b;
        const bool more = (t + 1 < NT);
        if (more) {
            a = *reinterpret_cast<const float4*>(Aptr + (t + 1) * BK);
            if (LNA) {
                const int kg = (t + 1) * BK + acol;
                float4 g  = *reinterpret_cast<const float4*>(gamma + kg);
                float4 be = *reinterpret_cast<const float4*>(beta + kg);
                a.x = (a.x - mu) * rs * g.x + be.x;
                a.y = (a.y - mu) * rs * g.y + be.y;
                a.z = (a.z - mu) * rs * g.z + be.z;
                a.w = (a.w - mu) * rs * g.w + be.w;
            }
            b = *reinterpret_cast<const float4*>(Bptr + (size_t)(t + 1) * BK * N);
        }

        #pragma unroll
        for (int k = 0; k < BK; k++) {
            float4 a0 = *reinterpret_cast<const float4*>(&As[buf][k][ty * TM]);
            float4 a1 = *reinterpret_cast<const float4*>(&As[buf][k][ty * TM + 4]);
            float4 b0 = *reinterpret_cast<const float4*>(&Bs[buf][k][tx * TN]);
            float4 b1 = *reinterpret_cast<const float4*>(&Bs[buf][k][tx * TN + 4]);
            float ra[TM] = {a0.x, a0.y, a0.z, a0.w, a1.x, a1.y, a1.z, a1.w};
            float rb[TN] = {b0.x, b0.y, b0.z, b0.w, b1.x, b1.y, b1.z, b1.w};
            #pragma unroll
            for (int i = 0; i < TM; i++)
                #pragma unroll
                for (int j = 0; j < TN; j++)
                    acc[i][j] = fmaf(ra[i], rb[j], acc[i][j]);
        }

        if (more) {
            As[buf ^ 1][acol + 0][arow] = a.x;
            As[buf ^ 1][acol + 1][arow] = a.y;
            As[buf ^ 1][acol + 2][arow] = a.z;
            As[buf ^ 1][acol + 3][arow] = a.w;
            *reinterpret_cast<float4*>(&Bs[buf ^ 1][brow][bcol]) = b;
            __syncthreads();
            buf ^= 1;
        }
    }

    // ---- epilogue ----
    #pragma unroll
    for (int i = 0; i < TM; i++) {
        const int row = bm + ty * TM + i;
        #pragma unroll
        for (int j = 0; j < TN; j += 4) {
            const int col = bn + tx * TN + j;
            float4 o;
            o.x = acc[i][j + 0] + bias[col + 0];
            o.y = acc[i][j + 1] + bias[col + 1];
            o.z = acc[i][j + 2] + bias[col + 2];
            o.w = acc[i][j + 3] + bias[col + 3];
            if (EPI == 0) {
                o.x = gelu_f(o.x); o.y = gelu_f(o.y);
                o.z = gelu_f(o.z); o.w = gelu_f(o.w);
            } else {
                const float4 r = *reinterpret_cast<const float4*>(
                    resid + (size_t)row * N + col);
                o.x += r.x; o.y += r.y; o.z += r.z; o.w += r.w;
            }
            *reinterpret_cast<float4*>(C + (size_t)row * N + col) = o;
        }
    }
}

// ---------------------------------------------------------------------------
extern "C" void kernel_launch(void* const* d_in, const int* in_sizes, int n_in,
                              void* d_out, int out_size) {
    const float* x     = (const float*)d_in[0];
    const float* gamma = (const float*)d_in[1];
    const float* beta  = (const float*)d_in[2];
    const float* W1    = (const float*)d_in[3];
    const float* b1    = (const float*)d_in[4];
    const float* W2    = (const float*)d_in[5];
    const float* b2    = (const float*)d_in[6];
    const float* W3    = (const float*)d_in[7];
    const float* b3    = (const float*)d_in[8];
    const float* W4    = (const float*)d_in[9];
    const float* b4    = (const float*)d_in[10];
    float* out = (float*)d_out;

    float *buf1 = nullptr, *buf2 = nullptr;
    cudaGetSymbolAddress((void**)&buf1, g_buf1);
    cudaGetSymbolAddress((void**)&buf2, g_buf2);

    rowstats_kernel<<<ROWS, 256>>>(x);

    // GEMM1: LN(x)[32768,1024] @ W1[1024,512] -> gelu -> buf1
    gemm_kernel<DIM, HMID, 0, true>
        <<<dim3(HMID / 128, ROWS / 128), 256>>>(x, W1, b1, buf1, gamma, beta, nullptr);
    // GEMM2: buf1 @ W2[512,512] -> gelu -> buf2
    gemm_kernel<HMID, HMID, 0, false>
        <<<dim3(HMID / 128, ROWS / 128), 256>>>(buf1, W2, b2, buf2, nullptr, nullptr, nullptr);
    // GEMM3: buf2 @ W3[512,256] -> gelu -> buf1
    gemm_kernel<HMID, HLOW, 0, false>
        <<<dim3(HLOW / 128, ROWS / 128), 256>>>(buf2, W3, b3, buf1, nullptr, nullptr, nullptr);
    // GEMM4: buf1 @ W4[256,1024] + b4 + x -> out
    gemm_kernel<HLOW, DIM, 1, false>
        <<<dim3(DIM / 128, ROWS / 128), 256>>>(buf1, W4, b4, out, nullptr, nullptr, x);
}

// round 3
// speedup vs baseline: 2.3239x; 2.3239x over previous
#include <cuda_runtime.h>
#include <math.h>
#include <stdint.h>

#define DIM   1024
#define HMID  512
#define HLOW  256
#define ROWS  32768   // 4 * 8192

// ---------------- scratch (device globals; allocation-free) ----------------
__device__ float g_ln  [ROWS * DIM];    // 128 MB  LN(x), tf32-rounded
__device__ float g_buf1[ROWS * HMID];   //  64 MB
__device__ float g_buf2[ROWS * HMID];   //  64 MB
__device__ float g_w1[DIM  * HMID];     // tf32-rounded weights
__device__ float g_w2[HMID * HMID];
__device__ float g_w3[HMID * HLOW];
__device__ float g_w4[HLOW * DIM];

// ---------------- helpers ----------------
__device__ __forceinline__ float tf32r(float x) {
    float y;
    asm("cvt.rna.tf32.f32 %0, %1;" : "=f"(y) : "f"(x));
    return y;
}
__device__ __forceinline__ float gelu_f(float v) {
    return 0.5f * v * (1.0f + erff(v * 0.70710678118654752440f));
}
__device__ __forceinline__ uint32_t smem_u32(const void* p) {
    uint32_t a;
    asm("{ .reg .u64 t; cvta.to.shared.u64 t, %1; cvt.u32.u64 %0, t; }" : "=r"(a) : "l"(p));
    return a;
}
__device__ __forceinline__ void cp16(uint32_t dst, const void* src) {
    asm volatile("cp.async.cg.shared.global [%0], [%1], 16;" :: "r"(dst), "l"(src));
}
__device__ __forceinline__ void cp_commit() {
    asm volatile("cp.async.commit_group;" ::: "memory");
}
template <int N>
__device__ __forceinline__ void cp_wait() {
    asm volatile("cp.async.wait_group %0;" :: "n"(N) : "memory");
}
__device__ __forceinline__ void mma_tf32(float* d, const float* a, const float* b) {
    asm volatile(
        "mma.sync.aligned.m16n8k8.row.col.f32.tf32.tf32.f32 "
        "{%0,%1,%2,%3}, {%4,%5,%6,%7}, {%8,%9}, {%0,%1,%2,%3};"
        : "+f"(d[0]), "+f"(d[1]), "+f"(d[2]), "+f"(d[3])
        : "f"(a[0]), "f"(a[1]), "f"(a[2]), "f"(a[3]), "f"(b[0]), "f"(b[1]));
}

// ---------------------------------------------------------------------------
// LayerNorm: one row per block, writes tf32-rounded LN(x)
// ---------------------------------------------------------------------------
__global__ void ln_kernel(const float* __restrict__ x, const float* __restrict__ gamma,
                          const float* __restrict__ beta, float* __restrict__ out) {
    const int row = blockIdx.x;
    const float4* xr = reinterpret_cast<const float4*>(x + (size_t)row * DIM);
    float4 v = xr[threadIdx.x];
    float s  = v.x + v.y + v.z + v.w;
    float sq = v.x * v.x + v.y * v.y + v.z * v.z + v.w * v.w;
    __shared__ float ss[8], ssq[8];
    __shared__ float s_mu, s_rs;
    #pragma unroll
    for (int o = 16; o > 0; o >>= 1) {
        s  += __shfl_down_sync(0xffffffffu, s,  o);
        sq += __shfl_down_sync(0xffffffffu, sq, o);
    }
    const int warp = threadIdx.x >> 5, lane = threadIdx.x & 31;
    if (lane == 0) { ss[warp] = s; ssq[warp] = sq; }
    __syncthreads();
    if (warp == 0) {
        s  = (lane < 8) ? ss[lane]  : 0.0f;
        sq = (lane < 8) ? ssq[lane] : 0.0f;
        #pragma unroll
        for (int o = 4; o > 0; o >>= 1) {
            s  += __shfl_down_sync(0xffffffffu, s,  o);
            sq += __shfl_down_sync(0xffffffffu, sq, o);
        }
        if (lane == 0) {
            float mu  = s * (1.0f / DIM);
            float var = sq * (1.0f / DIM) - mu * mu;
            s_mu = mu;
            s_rs = rsqrtf(var + 1e-5f);
        }
    }
    __syncthreads();
    const float mu = s_mu, rs = s_rs;
    const int c = threadIdx.x * 4;
    const float4 g  = *reinterpret_cast<const float4*>(gamma + c);
    const float4 be = *reinterpret_cast<const float4*>(beta + c);
    float4 o;
    o.x = tf32r((v.x - mu) * rs * g.x + be.x);
    o.y = tf32r((v.y - mu) * rs * g.y + be.y);
    o.z = tf32r((v.z - mu) * rs * g.z + be.z);
    o.w = tf32r((v.w - mu) * rs * g.w + be.w);
    *reinterpret_cast<float4*>(out + (size_t)row * DIM + c) = o;
}

// tf32-round copy (weights)
__global__ void round_copy(const float* __restrict__ src, float* __restrict__ dst, int n) {
    const int i = (blockIdx.x * blockDim.x + threadIdx.x) * 4;
    if (i < n) {
        float4 v = *reinterpret_cast<const float4*>(src + i);
        v.x = tf32r(v.x); v.y = tf32r(v.y); v.z = tf32r(v.z); v.w = tf32r(v.w);
        *reinterpret_cast<float4*>(dst + i) = v;
    }
}

// ---------------------------------------------------------------------------
// tf32 mma.sync GEMM: C[M,N] = epi(A[M,K] @ B[K,N] + bias)
//   BM=BN=128, BK=32, 256 threads (8 warps, 64x32 warp tiles, 2x4 grid),
//   cp.async double-buffered smem.  EPI 0: GELU(+tf32 round)  EPI 1: +resid
// ---------------------------------------------------------------------------
static constexpr int AS_STRIDE = 36;    // floats per A smem row  (128 rows)
static constexpr int BS_STRIDE = 132;   // floats per B smem row  (32 rows)
static constexpr int A_FLOATS  = 128 * AS_STRIDE;           // 4608
static constexpr int B_FLOATS  = 32 * BS_STRIDE;            // 4224
static constexpr int STAGE_FLOATS = A_FLOATS + B_FLOATS;    // 8832
static constexpr int SMEM_BYTES = 2 * STAGE_FLOATS * 4;     // 70656

template <int K, int N, int EPI>
__global__ void __launch_bounds__(256, 2)
mma_gemm(const float* __restrict__ A, const float* __restrict__ B,
         const float* __restrict__ bias, float* __restrict__ C,
         const float* __restrict__ resid) {
    constexpr int BM = 128, BN = 128, BK = 32;
    constexpr int NT = K / BK;
    extern __shared__ float sm[];
    const uint32_t sb = smem_u32(sm);
    const int bm = blockIdx.y * BM;
    const int bn = blockIdx.x * BN;
    const int tid  = threadIdx.x;
    const int warp = tid >> 5, lane = tid & 31;
    const int wm = warp >> 2, wn = warp & 3;     // warp tile: rows wm*64, cols wn*32
    const int g  = lane >> 2, tg = lane & 3;     // fragment lane decomposition

    float acc[4][4][4];
    #pragma unroll
    for (int mt = 0; mt < 4; mt++)
        #pragma unroll
        for (int nt = 0; nt < 4; nt++)
            #pragma unroll
            for (int r = 0; r < 4; r++) acc[mt][nt][r] = 0.0f;

    // ---- async tile loader ----
    auto load_tile = [&](int s, int t) {
        const uint32_t base = sb + (uint32_t)(s * STAGE_FLOATS * 4);
        #pragma unroll
        for (int j = 0; j < 4; j++) {            // A: 128x32 = 1024 16B chunks
            const int chunk = tid * 4 + j;
            const int r = chunk >> 3, c = chunk & 7;
            cp16(base + (uint32_t)(r * AS_STRIDE * 4 + c * 16),
                 A + (size_t)(bm + r) * K + t * BK + c * 4);
        }
        #pragma unroll
        for (int j = 0; j < 4; j++) {            // B: 32x128 = 1024 16B chunks
            const int chunk = tid * 4 + j;
            const int r = chunk >> 5, c = chunk & 31;
            cp16(base + (uint32_t)(A_FLOATS * 4 + r * BS_STRIDE * 4 + c * 16),
                 B + (size_t)(t * BK + r) * N + bn + c * 4);
        }
        cp_commit();
    };

    load_tile(0, 0);

    for (int t = 0; t < NT; t++) {
        if (t + 1 < NT) { load_tile((t + 1) & 1, t + 1); cp_wait<1>(); }
        else            { cp_wait<0>(); }
        __syncthreads();

        const float* As = sm + (t & 1) * STAGE_FLOATS;
        const float* Bs = As + A_FLOATS;
        #pragma unroll
        for (int k8 = 0; k8 < BK / 8; k8++) {
            const int k0 = k8 * 8;
            float a[4][4], b[4][2];
            #pragma unroll
            for (int mt = 0; mt < 4; mt++) {
                const int r0 = wm * 64 + mt * 16;
                a[mt][0] = As[(r0 + g)     * AS_STRIDE + k0 + tg];
                a[mt][1] = As[(r0 + g + 8) * AS_STRIDE + k0 + tg];
                a[mt][2] = As[(r0 + g)     * AS_STRIDE + k0 + tg + 4];
                a[mt][3] = As[(r0 + g + 8) * AS_STRIDE + k0 + tg + 4];
            }
            #pragma unroll
            for (int nt = 0; nt < 4; nt++) {
                const int c0 = wn * 32 + nt * 8 + g;
                b[nt][0] = Bs[(k0 + tg)     * BS_STRIDE + c0];
                b[nt][1] = Bs[(k0 + tg + 4) * BS_STRIDE + c0];
            }
            #pragma unroll
            for (int mt = 0; mt < 4; mt++)
                #pragma unroll
                for (int nt = 0; nt < 4; nt++)
                    mma_tf32(acc[mt][nt], a[mt], b[nt]);
        }
        __syncthreads();
    }

    // ---- epilogue ----
    #pragma unroll
    for (int mt = 0; mt < 4; mt++) {
        #pragma unroll
        for (int nt = 0; nt < 4; nt++) {
            const int col = bn + wn * 32 + nt * 8 + tg * 2;
            const float bx = __ldg(bias + col), by = __ldg(bias + col + 1);
            #pragma unroll
            for (int h = 0; h < 2; h++) {        // h=0: rows +0, h=1: rows +8
                const int row = bm + wm * 64 + mt * 16 + g + h * 8;
                float2 o;
                o.x = acc[mt][nt][2 * h + 0] + bx;
                o.y = acc[mt][nt][2 * h + 1] + by;
                if (EPI == 0) {
                    o.x = tf32r(gelu_f(o.x));
                    o.y = tf32r(gelu_f(o.y));
                } else {
                    const float2 rr = *reinterpret_cast<const float2*>(
                        resid + (size_t)row * N + col);
                    o.x += rr.x; o.y += rr.y;
                }
                *reinterpret_cast<float2*>(C + (size_t)row * N + col) = o;
            }
        }
    }
}

// ---------------------------------------------------------------------------
extern "C" void kernel_launch(void* const* d_in, const int* in_sizes, int n_in,
                              void* d_out, int out_size) {
    const float* x     = (const float*)d_in[0];
    const float* gamma = (const float*)d_in[1];
    const float* beta  = (const float*)d_in[2];
    const float* W1    = (const float*)d_in[3];
    const float* b1    = (const float*)d_in[4];
    const float* W2    = (const float*)d_in[5];
    const float* b2    = (const float*)d_in[6];
    const float* W3    = (const float*)d_in[7];
    const float* b3    = (const float*)d_in[8];
    const float* W4    = (const float*)d_in[9];
    const float* b4    = (const float*)d_in[10];
    float* out = (float*)d_out;

    float *ln, *buf1, *buf2, *w1, *w2, *w3, *w4;
    cudaGetSymbolAddress((void**)&ln,   g_ln);
    cudaGetSymbolAddress((void**)&buf1, g_buf1);
    cudaGetSymbolAddress((void**)&buf2, g_buf2);
    cudaGetSymbolAddress((void**)&w1,   g_w1);
    cudaGetSymbolAddress((void**)&w2,   g_w2);
    cudaGetSymbolAddress((void**)&w3,   g_w3);
    cudaGetSymbolAddress((void**)&w4,   g_w4);

    cudaFuncSetAttribute(mma_gemm<DIM,  HMID, 0>, cudaFuncAttributeMaxDynamicSharedMemorySize, SMEM_BYTES);
    cudaFuncSetAttribute(mma_gemm<HMID, HMID, 0>, cudaFuncAttributeMaxDynamicSharedMemorySize, SMEM_BYTES);
    cudaFuncSetAttribute(mma_gemm<HMID, HLOW, 0>, cudaFuncAttributeMaxDynamicSharedMemorySize, SMEM_BYTES);
    cudaFuncSetAttribute(mma_gemm<HLOW, DIM,  1>, cudaFuncAttributeMaxDynamicSharedMemorySize, SMEM_BYTES);

    ln_kernel<<<ROWS, 256>>>(x, gamma, beta, ln);
    round_copy<<<(DIM * HMID / 4 + 255) / 256, 256>>>(W1, w1, DIM * HMID);
    round_copy<<<(HMID * HMID / 4 + 255) / 256, 256>>>(W2, w2, HMID * HMID);
    round_copy<<<(HMID * HLOW / 4 + 255) / 256, 256>>>(W3, w3, HMID * HLOW);
    round_copy<<<(HLOW * DIM / 4 + 255) / 256, 256>>>(W4, w4, HLOW * DIM);

    // GEMM1: LN(x)[32768,1024] @ W1 -> gelu -> buf1
    mma_gemm<DIM, HMID, 0>
        <<<dim3(HMID / 128, ROWS / 128), 256, SMEM_BYTES>>>(ln, w1, b1, buf1, nullptr);
    // GEMM2: buf1 @ W2 -> gelu -> buf2
    mma_gemm<HMID, HMID, 0>
        <<<dim3(HMID / 128, ROWS / 128), 256, SMEM_BYTES>>>(buf1, w2, b2, buf2, nullptr);
    // GEMM3: buf2 @ W3 -> gelu -> buf1
    mma_gemm<HMID, HLOW, 0>
        <<<dim3(HLOW / 128, ROWS / 128), 256, SMEM_BYTES>>>(buf2, w3, b3, buf1, nullptr);
    // GEMM4: buf1 @ W4 + b4 + x -> out
    mma_gemm<HLOW, DIM, 1>
        <<<dim3(DIM / 128, ROWS / 128), 256, SMEM_BYTES>>>(buf1, w4, b4, out, x);
}

// round 5
// speedup vs baseline: 5.1063x; 2.1973x over previous
#include <cuda_runtime.h>
#include <cuda_fp16.h>
#include <math.h>
#include <stdint.h>

#define DIM   1024
#define HMID  512
#define HLOW  256
#define ROWS  32768   // 4 * 8192

// ---------------- scratch (device globals; allocation-free) ----------------
__device__ __half g_lnh [ROWS * DIM];    // 64 MB  LN(x) in fp16
__device__ __half g_buf1[ROWS * HMID];   // 32 MB
__device__ __half g_buf2[ROWS * HMID];   // 32 MB
__device__ __half g_w1h[DIM  * HMID];
__device__ __half g_w2h[HMID * HMID];
__device__ __half g_w3h[HMID * HLOW];
__device__ __half g_w4h[HLOW * DIM];

// ---------------- helpers ----------------
__device__ __forceinline__ uint32_t h2_bits(__half2 h) {
    union { __half2 h; uint32_t u; } c;
    c.h = h;
    return c.u;
}
__device__ __forceinline__ float gelu_f(float v) {
    return 0.5f * v * (1.0f + erff(v * 0.70710678118654752440f));
}
__device__ __forceinline__ uint32_t smem_u32(const void* p) {
    uint32_t a;
    asm("{ .reg .u64 t; cvta.to.shared.u64 t, %1; cvt.u32.u64 %0, t; }" : "=r"(a) : "l"(p));
    return a;
}
__device__ __forceinline__ void cp16(uint32_t dst, const void* src) {
    asm volatile("cp.async.cg.shared.global [%0], [%1], 16;" :: "r"(dst), "l"(src));
}
__device__ __forceinline__ void cp_commit() {
    asm volatile("cp.async.commit_group;" ::: "memory");
}
template <int N>
__device__ __forceinline__ void cp_wait() {
    asm volatile("cp.async.wait_group %0;" :: "n"(N) : "memory");
}
__device__ __forceinline__ void ldsm_x4(uint32_t* r, uint32_t addr) {
    asm volatile("ldmatrix.sync.aligned.m8n8.x4.shared.b16 {%0,%1,%2,%3}, [%4];"
        : "=r"(r[0]), "=r"(r[1]), "=r"(r[2]), "=r"(r[3]) : "r"(addr));
}
__device__ __forceinline__ void ldsm_x4_t(uint32_t* r, uint32_t addr) {
    asm volatile("ldmatrix.sync.aligned.m8n8.x4.trans.shared.b16 {%0,%1,%2,%3}, [%4];"
        : "=r"(r[0]), "=r"(r[1]), "=r"(r[2]), "=r"(r[3]) : "r"(addr));
}
__device__ __forceinline__ void mma_f16(float* d, const uint32_t* a, const uint32_t* b) {
    asm volatile(
        "mma.sync.aligned.m16n8k16.row.col.f32.f16.f16.f32 "
        "{%0,%1,%2,%3}, {%4,%5,%6,%7}, {%8,%9}, {%0,%1,%2,%3};"
        : "+f"(d[0]), "+f"(d[1]), "+f"(d[2]), "+f"(d[3])
        : "r"(a[0]), "r"(a[1]), "r"(a[2]), "r"(a[3]), "r"(b[0]), "r"(b[1]));
}

// ---------------------------------------------------------------------------
// LayerNorm -> fp16
// ---------------------------------------------------------------------------
__global__ void ln_kernel(const float* __restrict__ x, const float* __restrict__ gamma,
                          const float* __restrict__ beta, __half* __restrict__ out) {
    const int row = blockIdx.x;
    const float4* xr = reinterpret_cast<const float4*>(x + (size_t)row * DIM);
    float4 v = xr[threadIdx.x];
    float s  = v.x + v.y + v.z + v.w;
    float sq = v.x * v.x + v.y * v.y + v.z * v.z + v.w * v.w;
    __shared__ float ss[8], ssq[8];
    __shared__ float s_mu, s_rs;
    #pragma unroll
    for (int o = 16; o > 0; o >>= 1) {
        s  += __shfl_down_sync(0xffffffffu, s,  o);
        sq += __shfl_down_sync(0xffffffffu, sq, o);
    }
    const int warp = threadIdx.x >> 5, lane = threadIdx.x & 31;
    if (lane == 0) { ss[warp] = s; ssq[warp] = sq; }
    __syncthreads();
    if (warp == 0) {
        s  = (lane < 8) ? ss[lane]  : 0.0f;
        sq = (lane < 8) ? ssq[lane] : 0.0f;
        #pragma unroll
        for (int o = 4; o > 0; o >>= 1) {
            s  += __shfl_down_sync(0xffffffffu, s,  o);
            sq += __shfl_down_sync(0xffffffffu, sq, o);
        }
        if (lane == 0) {
            float mu  = s * (1.0f / DIM);
            float var = sq * (1.0f / DIM) - mu * mu;
            s_mu = mu;
            s_rs = rsqrtf(var + 1e-5f);
        }
    }
    __syncthreads();
    const float mu = s_mu, rs = s_rs;
    const int c = threadIdx.x * 4;
    const float4 g  = *reinterpret_cast<const float4*>(gamma + c);
    const float4 be = *reinterpret_cast<const float4*>(beta + c);
    __half2 h01 = __floats2half2_rn((v.x - mu) * rs * g.x + be.x,
                                    (v.y - mu) * rs * g.y + be.y);
    __half2 h23 = __floats2half2_rn((v.z - mu) * rs * g.z + be.z,
                                    (v.w - mu) * rs * g.w + be.w);
    uint2 pk = make_uint2(h2_bits(h01), h2_bits(h23));
    *reinterpret_cast<uint2*>(out + (size_t)row * DIM + c) = pk;
}

// fp32 -> fp16 weight conversion
__global__ void to_half(const float* __restrict__ src, __half* __restrict__ dst, int n) {
    const int i = (blockIdx.x * blockDim.x + threadIdx.x) * 4;
    if (i < n) {
        float4 v = *reinterpret_cast<const float4*>(src + i);
        __half2 h01 = __floats2half2_rn(v.x, v.y);
        __half2 h23 = __floats2half2_rn(v.z, v.w);
        uint2 pk = make_uint2(h2_bits(h01), h2_bits(h23));
        *reinterpret_cast<uint2*>(dst + i) = pk;
    }
}

// ---------------------------------------------------------------------------
// fp16 mma.sync GEMM: C[M,N] = epi(A[M,K] @ B[K,N] + bias)
//   BM=BN=128, BK=32 (halves), 8 warps (64x32 warp tiles), 3-stage cp.async,
//   ldmatrix fragment loads.  EPI 0: GELU -> fp16   EPI 1: +resid -> fp32
// ---------------------------------------------------------------------------
static constexpr int AS_STRIDE = 40;    // halves per A smem row (128 rows)
static constexpr int BS_STRIDE = 136;   // halves per B smem row (32 rows)
static constexpr int A_HALVES  = 128 * AS_STRIDE;             // 5120
static constexpr int STAGE_BYTES = (A_HALVES + 32 * BS_STRIDE) * 2;  // 18944
static constexpr int SMEM_BYTES  = 3 * STAGE_BYTES;                  // 56832

template <int K, int N, int EPI>
__global__ void __launch_bounds__(256, 2)
mma_gemm(const __half* __restrict__ A, const __half* __restrict__ B,
         const float* __restrict__ bias, void* __restrict__ Cv,
         const float* __restrict__ resid) {
    constexpr int BM = 128, BN = 128, BK = 32;
    constexpr int NT = K / BK;
    extern __shared__ __half sm[];
    const uint32_t sb = smem_u32(sm);
    const int bm = blockIdx.y * BM;
    const int bn = blockIdx.x * BN;
    const int tid  = threadIdx.x;
    const int warp = tid >> 5, lane = tid & 31;
    const int wm = warp >> 2, wn = warp & 3;     // warp tile rows wm*64, cols wn*32

    float acc[4][4][4];
    #pragma unroll
    for (int mt = 0; mt < 4; mt++)
        #pragma unroll
        for (int nt = 0; nt < 4; nt++)
            #pragma unroll
            for (int r = 0; r < 4; r++) acc[mt][nt][r] = 0.0f;

    auto load_tile = [&](int s, int t) {
        const uint32_t base = sb + (uint32_t)(s * STAGE_BYTES);
        #pragma unroll
        for (int j = 0; j < 2; j++) {            // A: 128x32 halves = 512 chunks
            const int chunk = tid * 2 + j;
            const int r = chunk >> 2, c = chunk & 3;
            cp16(base + (uint32_t)(r * AS_STRIDE + c * 8) * 2,
                 A + (size_t)(bm + r) * K + t * BK + c * 8);
        }
        #pragma unroll
        for (int j = 0; j < 2; j++) {            // B: 32x128 halves = 512 chunks
            const int chunk = tid * 2 + j;
            const int r = chunk >> 4, c = chunk & 15;
            cp16(base + (uint32_t)(A_HALVES + r * BS_STRIDE + c * 8) * 2,
                 B + (size_t)(t * BK + r) * N + bn + c * 8);
        }
        cp_commit();
    };

    load_tile(0, 0);
    if (NT > 1) load_tile(1, 1);

    for (int t = 0; t < NT; t++) {
        if (t + 1 < NT) cp_wait<1>(); else cp_wait<0>();
        __syncthreads();
        if (t + 2 < NT) load_tile((t + 2) % 3, t + 2);

        const uint32_t As = sb + (uint32_t)((t % 3) * STAGE_BYTES);
        const uint32_t Bs = As + A_HALVES * 2;
        #pragma unroll
        for (int kk = 0; kk < BK / 16; kk++) {
            const int k0 = kk * 16;
            uint32_t a[4][4], b[2][4];
            #pragma unroll
            for (int mt = 0; mt < 4; mt++) {
                const int row = wm * 64 + mt * 16 + (lane & 15);
                ldsm_x4(a[mt], As + (uint32_t)(row * AS_STRIDE + k0 + 8 * (lane >> 4)) * 2);
            }
            #pragma unroll
            for (int np = 0; np < 2; np++) {
                const int row = k0 + (lane & 15);
                ldsm_x4_t(b[np], Bs + (uint32_t)(row * BS_STRIDE + wn * 32 + np * 16
                                                 + 8 * (lane >> 4)) * 2);
            }
            #pragma unroll
            for (int mt = 0; mt < 4; mt++)
                #pragma unroll
                for (int nt = 0; nt < 4; nt++)
                    mma_f16(acc[mt][nt], a[mt], &b[nt >> 1][(nt & 1) * 2]);
        }
        __syncthreads();
    }

    // ---- epilogue ----
    const int g = lane >> 2, tg = lane & 3;
    #pragma unroll
    for (int mt = 0; mt < 4; mt++) {
        #pragma unroll
        for (int nt = 0; nt < 4; nt++) {
            const int col = bn + wn * 32 + nt * 8 + tg * 2;
            const float bx = __ldg(bias + col), by = __ldg(bias + col + 1);
            #pragma unroll
            for (int h = 0; h < 2; h++) {
                const int row = bm + wm * 64 + mt * 16 + g + h * 8;
                float ox = acc[mt][nt][2 * h + 0] + bx;
                float oy = acc[mt][nt][2 * h + 1] + by;
                if (EPI == 0) {
                    __half2 hv = __floats2half2_rn(gelu_f(ox), gelu_f(oy));
                    *reinterpret_cast<__half2*>((__half*)Cv + (size_t)row * N + col) = hv;
                } else {
                    const float2 rr = *reinterpret_cast<const float2*>(
                        resid + (size_t)row * N + col);
                    float2 o; o.x = ox + rr.x; o.y = oy + rr.y;
                    *reinterpret_cast<float2*>((float*)Cv + (size_t)row * N + col) = o;
                }
            }
        }
    }
}

// ---------------------------------------------------------------------------
extern "C" void kernel_launch(void* const* d_in, const int* in_sizes, int n_in,
                              void* d_out, int out_size) {
    const float* x     = (const float*)d_in[0];
    const float* gamma = (const float*)d_in[1];
    const float* beta  = (const float*)d_in[2];
    const float* W1    = (const float*)d_in[3];
    const float* b1    = (const float*)d_in[4];
    const float* W2    = (const float*)d_in[5];
    const float* b2    = (const float*)d_in[6];
    const float* W3    = (const float*)d_in[7];
    const float* b3    = (const float*)d_in[8];
    const float* W4    = (const float*)d_in[9];
    const float* b4    = (const float*)d_in[10];
    float* out = (float*)d_out;

    __half *ln, *buf1, *buf2, *w1, *w2, *w3, *w4;
    cudaGetSymbolAddress((void**)&ln,   g_lnh);
    cudaGetSymbolAddress((void**)&buf1, g_buf1);
    cudaGetSymbolAddress((void**)&buf2, g_buf2);
    cudaGetSymbolAddress((void**)&w1,   g_w1h);
    cudaGetSymbolAddress((void**)&w2,   g_w2h);
    cudaGetSymbolAddress((void**)&w3,   g_w3h);
    cudaGetSymbolAddress((void**)&w4,   g_w4h);

    cudaFuncSetAttribute(mma_gemm<DIM,  HMID, 0>, cudaFuncAttributeMaxDynamicSharedMemorySize, SMEM_BYTES);
    cudaFuncSetAttribute(mma_gemm<HMID, HMID, 0>, cudaFuncAttributeMaxDynamicSharedMemorySize, SMEM_BYTES);
    cudaFuncSetAttribute(mma_gemm<HMID, HLOW, 0>, cudaFuncAttributeMaxDynamicSharedMemorySize, SMEM_BYTES);
    cudaFuncSetAttribute(mma_gemm<HLOW, DIM,  1>, cudaFuncAttributeMaxDynamicSharedMemorySize, SMEM_BYTES);

    ln_kernel<<<ROWS, 256>>>(x, gamma, beta, ln);
    to_half<<<(DIM * HMID / 4 + 255) / 256, 256>>>(W1, w1, DIM * HMID);
    to_half<<<(HMID * HMID / 4 + 255) / 256, 256>>>(W2, w2, HMID * HMID);
    to_half<<<(HMID * HLOW / 4 + 255) / 256, 256>>>(W3, w3, HMID * HLOW);
    to_half<<<(HLOW * DIM / 4 + 255) / 256, 256>>>(W4, w4, HLOW * DIM);

    // GEMM1: LN(x)[32768,1024] @ W1 -> gelu -> buf1 (fp16)
    mma_gemm<DIM, HMID, 0>
        <<<dim3(HMID / 128, ROWS / 128), 256, SMEM_BYTES>>>(ln, w1, b1, buf1, nullptr);
    // GEMM2: buf1 @ W2 -> gelu -> buf2 (fp16)
    mma_gemm<HMID, HMID, 0>
        <<<dim3(HMID / 128, ROWS / 128), 256, SMEM_BYTES>>>(buf1, w2, b2, buf2, nullptr);
    // GEMM3: buf2 @ W3 -> gelu -> buf1 (fp16)
    mma_gemm<HMID, HLOW, 0>
        <<<dim3(HLOW / 128, ROWS / 128), 256, SMEM_BYTES>>>(buf2, w3, b3, buf1, nullptr);
    // GEMM4: buf1 @ W4 + b4 + x -> out (fp32)
    mma_gemm<HLOW, DIM, 1>
        <<<dim3(DIM / 128, ROWS / 128), 256, SMEM_BYTES>>>(buf1, w4, b4, out, x);
}